// round 8
// baseline (speedup 1.0000x reference)
#include <cuda_runtime.h>
#include <math.h>

// BinEmbedding: out[p] = emb_table[tok(x[p])]
//   tok = 0 if isnan(x), else clamp(count(bins <= x) - 1, 0) + 1
//
// x (B*L,) f32, bins (256,) f32, emb_table (257*64,) f32,
// out (B*L, 64) f32 = 268 MB written.
//
// Converged design at the LTS write-drain cap (~6.3 TB/s wall-clock).
// R8 = R7 (PPB 256 / grid 4096 / .cs stores) with the copy phase fully
// unrolled: all 16 gathers in flight before the stores drain (MLP=16).
// Occupancy drop from the register cost is non-binding (proven in R4).

#define NUM_BINS 256
#define F4_PER_ROW 16                    // 64 floats / 4
#define THREADS 256
#define PPB 256                          // positions per block
#define COPY_ITERS (PPB * F4_PER_ROW / THREADS)   // 16, fully unrolled

__global__ __launch_bounds__(THREADS) void bin_embed_kernel(
    const float*  __restrict__ x,
    const float*  __restrict__ bins,
    const float4* __restrict__ emb4,     // (NUM_BINS+1) * 16 float4
    float4*       __restrict__ out)      // n_pos * 16 float4
{
    __shared__ float sbins[NUM_BINS];
    __shared__ int   stok[PPB];

    const int tid  = threadIdx.x;
    const int base = blockIdx.x * PPB;

    sbins[tid] = bins[tid];              // THREADS == NUM_BINS
    __syncthreads();

    // ---- Phase 1: one search per thread ----
    {
        float v = __ldg(&x[base + tid]);
        int c = 0;
        bool nn = isnan(v);
        #pragma unroll
        for (int s = NUM_BINS >> 1; s > 0; s >>= 1) {
            if (sbins[c + s - 1] <= v) c += s;
        }
        int i0 = c - 1; if (i0 < 0) i0 = 0;
        stok[tid] = nn ? 0 : i0 + 1;
    }
    __syncthreads();

    // ---- Phase 2: single fully-unrolled gather burst, then store burst ----
    // float4 element index = tid + k*THREADS; sub = tid & 15 invariant;
    // row = (tid>>4) + k*16.
    const int sub = tid & 15;
    const int row0 = tid >> 4;
    float4* outp  = out + (size_t)base * F4_PER_ROW + tid;

    int tok[COPY_ITERS];
    #pragma unroll
    for (int k = 0; k < COPY_ITERS; k++)
        tok[k] = stok[row0 + k * 16];

    float4 val[COPY_ITERS];
    #pragma unroll
    for (int k = 0; k < COPY_ITERS; k++)
        val[k] = __ldg(&emb4[tok[k] * F4_PER_ROW + sub]);

    #pragma unroll
    for (int k = 0; k < COPY_ITERS; k++)
        __stcs(outp + (size_t)k * THREADS, val[k]);
}

extern "C" void kernel_launch(void* const* d_in, const int* in_sizes, int n_in,
                              void* d_out, int out_size)
{
    const float*  x    = (const float*)d_in[0];
    const float*  bins = (const float*)d_in[1];
    const float4* emb4 = (const float4*)d_in[2];
    float4* out = (float4*)d_out;

    int n_pos  = in_sizes[0];            // 1,048,576; divisible by PPB
    int blocks = n_pos / PPB;            // 4096

    bin_embed_kernel<<<blocks, THREADS>>>(x, bins, emb4, out);
}